// round 12
// baseline (speedup 1.0000x reference)
#include <cuda_runtime.h>
#include <math.h>

#define N_ATOMS 16384
#define N_EDGES 262144
#define HID 128
#define NG 50
#define NINTER 6

// padded strides (in floats) for conflict-free smem access
#define W_S  160   // weight row stride: 8 groups of 16 floats, each group padded to 20
#define EA_S 53    // ea tile row stride (odd -> distinct banks across row-groups)
#define T_S  133   // intermediate tile row stride (odd)
#define H_S  132   // node-side activation stride (multiple of 4 for float4 stores)

// ---------------- scratch (static device globals; no allocation) ----------------
__device__ float g_ea[N_EDGES * NG];     // 52.4 MB  gaussian smearing, iteration-invariant
__device__ float g_C[N_EDGES];           // cosine cutoff
__device__ float g_h[N_ATOMS * HID];     // node features
__device__ float g_x[N_ATOMS * HID];     // lin1 output
__device__ float g_agg[N_ATOMS * HID];   // scatter-sum target
__device__ float g_bsum[128];            // readout partials

// ---------------- helpers ----------------
__device__ __forceinline__ unsigned long long pack2(float lo, float hi) {
    unsigned long long r;
    asm("mov.b64 %0, {%1, %2};" : "=l"(r) : "f"(lo), "f"(hi));
    return r;
}
__device__ __forceinline__ void fma2(unsigned long long& d, unsigned long long a, unsigned long long b) {
    asm("fma.rn.f32x2 %0, %1, %2, %0;" : "+l"(d) : "l"(a), "l"(b));
}
__device__ __forceinline__ float2 unpack2(unsigned long long v) {
    float2 f;
    asm("mov.b64 {%0, %1}, %2;" : "=f"(f.x), "=f"(f.y) : "l"(v));
    return f;
}
__device__ __forceinline__ float sspf(float x) {
    return fmaxf(x, 0.0f) + log1pf(__expf(-fabsf(x))) - 0.6931471805599453f;
}

// software-pipelined GEMM microkernel:
// acc[2 rows][8 col-pairs] += a(row,k) * W(k, 16 cols), k = 0..K-1.
// sW points at this thread's column group (already offset by wg); row stride W_S.
// a0p/a1p point at the two activation rows (k-stride 1).
// Weights and activations for k+1 are prefetched into registers before the
// 16 fma2 of iteration k issue -> LDS latency hidden by a full iteration.
__device__ __forceinline__ void mk_gemm(const float* __restrict__ sW, int K,
                                        const float* __restrict__ a0p,
                                        const float* __restrict__ a1p,
                                        unsigned long long (&acc0)[8],
                                        unsigned long long (&acc1)[8]) {
    const ulonglong2* wp = (const ulonglong2*)sW;
    ulonglong2 w01 = wp[0], w23 = wp[1], w45 = wp[2], w67 = wp[3];
    float a0 = a0p[0], a1 = a1p[0];
#pragma unroll 2
    for (int k = 0; k < K - 1; k++) {
        const ulonglong2* wn = (const ulonglong2*)(sW + (k + 1) * W_S);
        ulonglong2 n01 = wn[0], n23 = wn[1], n45 = wn[2], n67 = wn[3];
        float na0 = a0p[k + 1], na1 = a1p[k + 1];
        unsigned long long b0 = pack2(a0, a0), b1 = pack2(a1, a1);
        fma2(acc0[0], b0, w01.x); fma2(acc0[1], b0, w01.y);
        fma2(acc0[2], b0, w23.x); fma2(acc0[3], b0, w23.y);
        fma2(acc0[4], b0, w45.x); fma2(acc0[5], b0, w45.y);
        fma2(acc0[6], b0, w67.x); fma2(acc0[7], b0, w67.y);
        fma2(acc1[0], b1, w01.x); fma2(acc1[1], b1, w01.y);
        fma2(acc1[2], b1, w23.x); fma2(acc1[3], b1, w23.y);
        fma2(acc1[4], b1, w45.x); fma2(acc1[5], b1, w45.y);
        fma2(acc1[6], b1, w67.x); fma2(acc1[7], b1, w67.y);
        w01 = n01; w23 = n23; w45 = n45; w67 = n67;
        a0 = na0; a1 = na1;
    }
    {
        unsigned long long b0 = pack2(a0, a0), b1 = pack2(a1, a1);
        fma2(acc0[0], b0, w01.x); fma2(acc0[1], b0, w01.y);
        fma2(acc0[2], b0, w23.x); fma2(acc0[3], b0, w23.y);
        fma2(acc0[4], b0, w45.x); fma2(acc0[5], b0, w45.y);
        fma2(acc0[6], b0, w67.x); fma2(acc0[7], b0, w67.y);
        fma2(acc1[0], b1, w01.x); fma2(acc1[1], b1, w01.y);
        fma2(acc1[2], b1, w23.x); fma2(acc1[3], b1, w23.y);
        fma2(acc1[4], b1, w45.x); fma2(acc1[5], b1, w45.y);
        fma2(acc1[6], b1, w67.x); fma2(acc1[7], b1, w67.y);
    }
}

// copy an n x 128 row-major weight matrix into padded layout (row stride W_S,
// group g at offset g*20). n4 = n*32 float4 elements.
__device__ __forceinline__ void load_w_padded(float* dst, const float* src, int n4, int tid, int nthr) {
    const float4* s4 = (const float4*)src;
    for (int idx = tid; idx < n4; idx += nthr) {
        int row = idx >> 5, q = idx & 31;
        int g = q >> 2, o = q & 3;
        ((float4*)(dst + row * W_S + g * 20))[o] = s4[idx];
    }
}

// ---------------- K0: per-edge geometry (once per launch) ----------------
__global__ __launch_bounds__(256) void geom_kernel(const int* __restrict__ ei,
                                                   const float* __restrict__ pos) {
    int idx = blockIdx.x * 256 + threadIdx.x;          // E*NG threads
    int e = idx / NG;
    int g = idx - e * NG;
    int s = ei[e];
    int d = ei[N_EDGES + e];
    float dx = pos[s * 3 + 0] - pos[d * 3 + 0];
    float dy = pos[s * 3 + 1] - pos[d * 3 + 1];
    float dz = pos[s * 3 + 2] - pos[d * 3 + 2];
    float dist = sqrtf(dx * dx + dy * dy + dz * dz);
    const float delta = 10.0f / 49.0f;
    const float coeff = -0.5f / (delta * delta);
    float t = dist - (float)g * delta;
    g_ea[idx] = __expf(coeff * t * t);
    if (g == 0) g_C[e] = 0.5f * (__cosf(dist * 0.31415926535897931f) + 1.0f);
}

// ---------------- K0b: h = emb[z] ----------------
__global__ __launch_bounds__(256) void init_h_kernel(const int* __restrict__ z,
                                                     const float* __restrict__ emb) {
    int idx = blockIdx.x * 256 + threadIdx.x;          // N*HID threads
    int n = idx >> 7;
    int c = idx & 127;
    g_h[idx] = emb[z[n] * HID + c];
}

// ---------------- K1: x = h @ Wl1[i]; also zeroes g_agg rows ----------------
#define SMEM_LIN1 ((128 * W_S + 64 * H_S) * 4)
__global__ __launch_bounds__(256, 1) void lin1_kernel(const float* __restrict__ W) {
    extern __shared__ float sm[];
    float* sW = sm;                 // 128 x W_S (padded groups)
    float* sH = sW + 128 * W_S;     // 64 x H_S
    int tid = threadIdx.x;
    int r0b = blockIdx.x * 64;

    // zero agg rows this block owns (edge kernel runs strictly after on same stream)
    {
        float4 z4 = make_float4(0.f, 0.f, 0.f, 0.f);
        float4* ap = (float4*)(g_agg + (size_t)r0b * HID);
        for (int idx = tid; idx < 2048; idx += 256) ap[idx] = z4;
    }

    load_w_padded(sW, W, 4096, tid, 256);
    {
        const float4* hsrc = (const float4*)(g_h + (size_t)r0b * HID);
        for (int idx = tid; idx < 2048; idx += 256) {
            int r = idx >> 5, q = idx & 31;
            ((float4*)(sH + r * H_S))[q] = hsrc[idx];
        }
    }
    __syncthreads();

    int cg = tid & 7, rg = tid >> 3;
    int c0 = cg * 16, r0 = rg * 2;
    int wg = cg * 20;

    unsigned long long acc0[8], acc1[8];
#pragma unroll
    for (int j = 0; j < 8; j++) { acc0[j] = 0ull; acc1[j] = 0ull; }

    mk_gemm(sW + wg, HID, sH + r0 * H_S, sH + (r0 + 1) * H_S, acc0, acc1);

#pragma unroll
    for (int r = 0; r < 2; r++) {
        unsigned long long* acc = r ? acc1 : acc0;
        float4* op = (float4*)(g_x + (size_t)(r0b + r0 + r) * HID + c0);
#pragma unroll
        for (int q = 0; q < 4; q++) {
            float2 p0 = unpack2(acc[2 * q]);
            float2 p1 = unpack2(acc[2 * q + 1]);
            float4 v; v.x = p0.x; v.y = p0.y; v.z = p1.x; v.w = p1.y;
            op[q] = v;
        }
    }
}

// ---------------- K2: fused edge kernel ----------------
#define SMEM_EDGE ((50 * W_S + 128 * W_S + 128 * EA_S + 128 * T_S + 3 * 128 + 256) * 4)
__global__ __launch_bounds__(512, 1) void edge_kernel(const float* __restrict__ Wf1,
                                                      const float* __restrict__ bf1,
                                                      const float* __restrict__ Wf2,
                                                      const float* __restrict__ bf2,
                                                      const int* __restrict__ ei) {
    extern __shared__ float sm[];
    float* sW1 = sm;                        // 50 x W_S
    float* sW2 = sW1 + 50 * W_S;            // 128 x W_S
    float* sEA = sW2 + 128 * W_S;           // 128 x EA_S
    float* sT  = sEA + 128 * EA_S;          // 128 x T_S
    float* sC  = sT + 128 * T_S;
    float* sB1 = sC + 128;
    float* sB2 = sB1 + 128;
    int* sSrc  = (int*)(sB2 + 128);
    int* sDst  = sSrc + 128;

    int tid = threadIdx.x;
    int e0b = blockIdx.x * 128;

    load_w_padded(sW1, Wf1, 1600, tid, 512);
    load_w_padded(sW2, Wf2, 4096, tid, 512);
    for (int idx = tid; idx < 128 * NG; idx += 512) {
        int e = idx / NG, k = idx - e * NG;
        sEA[e * EA_S + k] = g_ea[(size_t)e0b * NG + idx];
    }
    if (tid < 128) {
        sC[tid]  = g_C[e0b + tid];
        sB1[tid] = bf1[tid];
        sB2[tid] = bf2[tid];
        sSrc[tid] = ei[e0b + tid];
        sDst[tid] = ei[N_EDGES + e0b + tid];
    }
    __syncthreads();

    int cg = tid & 7, eg = tid >> 3;   // 8 col-groups x 64 edge-groups
    int c0 = cg * 16, e0 = eg * 2;
    int wg = cg * 20;

    unsigned long long acc0[8], acc1[8];
#pragma unroll
    for (int j = 0; j < 8; j++) { acc0[j] = 0ull; acc1[j] = 0ull; }

    // ---- phase 1: T = ssp(EA @ W1 + b1) ----
    mk_gemm(sW1 + wg, NG, sEA + e0 * EA_S, sEA + (e0 + 1) * EA_S, acc0, acc1);

#pragma unroll
    for (int e = 0; e < 2; e++) {
        unsigned long long* acc = e ? acc1 : acc0;
        float* trow = sT + (e0 + e) * T_S + c0;
#pragma unroll
        for (int q = 0; q < 4; q++) {
            float2 p0 = unpack2(acc[2 * q]);
            float2 p1 = unpack2(acc[2 * q + 1]);
            trow[4 * q + 0] = sspf(p0.x + sB1[c0 + 4 * q + 0]);
            trow[4 * q + 1] = sspf(p0.y + sB1[c0 + 4 * q + 1]);
            trow[4 * q + 2] = sspf(p1.x + sB1[c0 + 4 * q + 2]);
            trow[4 * q + 3] = sspf(p1.y + sB1[c0 + 4 * q + 3]);
        }
    }
    __syncthreads();

    // ---- phase 2: Wf = (T @ W2 + b2)*C; msg = x[src]*Wf; atomicAdd into agg[dst] ----
#pragma unroll
    for (int j = 0; j < 8; j++) { acc0[j] = 0ull; acc1[j] = 0ull; }

    mk_gemm(sW2 + wg, HID, sT + e0 * T_S, sT + (e0 + 1) * T_S, acc0, acc1);

#pragma unroll
    for (int e = 0; e < 2; e++) {
        unsigned long long* acc = e ? acc1 : acc0;
        int le = e0 + e;
        float Cv = sC[le];
        int s = sSrc[le];
        int d = sDst[le];
        const float4* xp = (const float4*)(g_x + (size_t)s * HID + c0);
        float* ap = g_agg + (size_t)d * HID + c0;
#pragma unroll
        for (int q = 0; q < 4; q++) {
            float2 p0 = unpack2(acc[2 * q]);
            float2 p1 = unpack2(acc[2 * q + 1]);
            float4 xv = xp[q];
            atomicAdd(ap + 4 * q + 0, (p0.x + sB2[c0 + 4 * q + 0]) * Cv * xv.x);
            atomicAdd(ap + 4 * q + 1, (p0.y + sB2[c0 + 4 * q + 1]) * Cv * xv.y);
            atomicAdd(ap + 4 * q + 2, (p1.x + sB2[c0 + 4 * q + 2]) * Cv * xv.z);
            atomicAdd(ap + 4 * q + 3, (p1.y + sB2[c0 + 4 * q + 3]) * Cv * xv.w);
        }
    }
}

// ---------------- K3: h = h + ssp(agg @ Wl2 + bl2) @ Wl + bl ----------------
// sA and sM overlay one buffer (regs hold GEMM1 result across a barrier).
#define SMEM_NODE ((2 * 128 * W_S + 64 * H_S + 256) * 4)
__global__ __launch_bounds__(256, 1) void node_kernel(const float* __restrict__ Wl2,
                                                      const float* __restrict__ bl2,
                                                      const float* __restrict__ Wl,
                                                      const float* __restrict__ bl) {
    extern __shared__ float sm[];
    float* sWa = sm;                      // Wl2, 128 x W_S
    float* sWb = sWa + 128 * W_S;         // Wl,  128 x W_S
    float* sAM = sWb + 128 * W_S;         // 64 x H_S (agg, then ssp result)
    float* sB2 = sAM + 64 * H_S;
    float* sB  = sB2 + 128;

    int tid = threadIdx.x;
    int r0b = blockIdx.x * 64;

    load_w_padded(sWa, Wl2, 4096, tid, 256);
    load_w_padded(sWb, Wl, 4096, tid, 256);
    {
        const float4* asrc = (const float4*)(g_agg + (size_t)r0b * HID);
        for (int idx = tid; idx < 2048; idx += 256) {
            int r = idx >> 5, q = idx & 31;
            ((float4*)(sAM + r * H_S))[q] = asrc[idx];
        }
    }
    if (tid < 128) { sB2[tid] = bl2[tid]; sB[tid] = bl[tid]; }
    __syncthreads();

    int cg = tid & 7, rg = tid >> 3;
    int c0 = cg * 16, r0 = rg * 2;
    int wg = cg * 20;

    unsigned long long acc0[8], acc1[8];
#pragma unroll
    for (int j = 0; j < 8; j++) { acc0[j] = 0ull; acc1[j] = 0ull; }

    mk_gemm(sWa + wg, HID, sAM + r0 * H_S, sAM + (r0 + 1) * H_S, acc0, acc1);

    __syncthreads();   // everyone done READING sAM before it is overwritten
#pragma unroll
    for (int r = 0; r < 2; r++) {
        unsigned long long* acc = r ? acc1 : acc0;
        float* mrow = sAM + (r0 + r) * H_S + c0;
#pragma unroll
        for (int q = 0; q < 4; q++) {
            float2 p0 = unpack2(acc[2 * q]);
            float2 p1 = unpack2(acc[2 * q + 1]);
            float4 v;
            v.x = sspf(p0.x + sB2[c0 + 4 * q + 0]);
            v.y = sspf(p0.y + sB2[c0 + 4 * q + 1]);
            v.z = sspf(p1.x + sB2[c0 + 4 * q + 2]);
            v.w = sspf(p1.y + sB2[c0 + 4 * q + 3]);
            ((float4*)mrow)[q] = v;
        }
    }
    __syncthreads();

#pragma unroll
    for (int j = 0; j < 8; j++) { acc0[j] = 0ull; acc1[j] = 0ull; }

    mk_gemm(sWb + wg, HID, sAM + r0 * H_S, sAM + (r0 + 1) * H_S, acc0, acc1);

#pragma unroll
    for (int r = 0; r < 2; r++) {
        unsigned long long* acc = r ? acc1 : acc0;
        float4* hp = (float4*)(g_h + (size_t)(r0b + r0 + r) * HID + c0);
#pragma unroll
        for (int q = 0; q < 4; q++) {
            float2 p0 = unpack2(acc[2 * q]);
            float2 p1 = unpack2(acc[2 * q + 1]);
            float4 h = hp[q];
            h.x += p0.x + sB[c0 + 4 * q + 0];
            h.y += p0.y + sB[c0 + 4 * q + 1];
            h.z += p1.x + sB[c0 + 4 * q + 2];
            h.w += p1.y + sB[c0 + 4 * q + 3];
            hp[q] = h;
        }
    }
}

// ---------------- K4: per-atom readout, per-block partial sums ----------------
__global__ __launch_bounds__(128) void readout_kernel(const float* __restrict__ Wo1,
                                                      const float* __restrict__ bo1,
                                                      const float* __restrict__ Wo2) {
    __shared__ float sW[128 * 64];
    __shared__ float sw2[64];
    __shared__ float sb1[64];
    __shared__ float wsum[4];
    int tid = threadIdx.x;
    for (int idx = tid; idx < 2048; idx += 128)
        ((float4*)sW)[idx] = ((const float4*)Wo1)[idx];
    if (tid < 64) { sw2[tid] = Wo2[tid]; sb1[tid] = bo1[tid]; }
    __syncthreads();

    int atom = blockIdx.x * 128 + tid;
    float acc[64];
#pragma unroll
    for (int j = 0; j < 64; j++) acc[j] = 0.0f;
    const float4* hp = (const float4*)(g_h + (size_t)atom * HID);
#pragma unroll 2
    for (int k4 = 0; k4 < 32; k4++) {
        float4 hv = hp[k4];
        const float* w0 = sW + (k4 * 4) * 64;
#pragma unroll
        for (int j = 0; j < 64; j++)
            acc[j] += hv.x * w0[j] + hv.y * w0[64 + j] + hv.z * w0[128 + j] + hv.w * w0[192 + j];
    }
    float s = 0.0f;
#pragma unroll
    for (int j = 0; j < 64; j++) s += sspf(acc[j] + sb1[j]) * sw2[j];

    for (int o = 16; o > 0; o >>= 1) s += __shfl_down_sync(0xffffffffu, s, o);
    if ((tid & 31) == 0) wsum[tid >> 5] = s;
    __syncthreads();
    if (tid == 0) g_bsum[blockIdx.x] = wsum[0] + wsum[1] + wsum[2] + wsum[3];
}

__global__ void finalize_kernel(const float* __restrict__ bo2, float* __restrict__ out) {
    __shared__ float ws[4];
    int tid = threadIdx.x;  // 128
    float v = g_bsum[tid];
    for (int o = 16; o > 0; o >>= 1) v += __shfl_down_sync(0xffffffffu, v, o);
    if ((tid & 31) == 0) ws[tid >> 5] = v;
    __syncthreads();
    if (tid == 0) {
        float t = ws[0] + ws[1] + ws[2] + ws[3] + (float)N_ATOMS * bo2[0];
        out[0] = fmaxf(t, 0.0f);
    }
}

// ---------------- launch ----------------
extern "C" void kernel_launch(void* const* d_in, const int* in_sizes, int n_in,
                              void* d_out, int out_size) {
    const int*   z    = (const int*)d_in[0];
    const float* pos  = (const float*)d_in[1];
    const int*   ei   = (const int*)d_in[2];
    const float* emb  = (const float*)d_in[3];
    const float* Wf1  = (const float*)d_in[4];
    const float* bf1  = (const float*)d_in[5];
    const float* Wf2  = (const float*)d_in[6];
    const float* bf2  = (const float*)d_in[7];
    const float* Wl1  = (const float*)d_in[8];
    const float* Wl2  = (const float*)d_in[9];
    const float* bl2  = (const float*)d_in[10];
    const float* Wl   = (const float*)d_in[11];
    const float* bl   = (const float*)d_in[12];
    const float* Wo1  = (const float*)d_in[13];
    const float* bo1  = (const float*)d_in[14];
    const float* Wo2  = (const float*)d_in[15];
    const float* bo2  = (const float*)d_in[16];
    float* out = (float*)d_out;

    cudaFuncSetAttribute(lin1_kernel, cudaFuncAttributeMaxDynamicSharedMemorySize, SMEM_LIN1);
    cudaFuncSetAttribute(edge_kernel, cudaFuncAttributeMaxDynamicSharedMemorySize, SMEM_EDGE);
    cudaFuncSetAttribute(node_kernel, cudaFuncAttributeMaxDynamicSharedMemorySize, SMEM_NODE);

    geom_kernel<<<(N_EDGES * NG) / 256, 256>>>(ei, pos);
    init_h_kernel<<<(N_ATOMS * HID) / 256, 256>>>(z, emb);

    for (int i = 0; i < NINTER; i++) {
        lin1_kernel<<<N_ATOMS / 64, 256, SMEM_LIN1>>>(Wl1 + i * 16384);
        edge_kernel<<<N_EDGES / 128, 512, SMEM_EDGE>>>(Wf1 + i * 6400, bf1 + i * 128,
                                                       Wf2 + i * 16384, bf2 + i * 128, ei);
        node_kernel<<<N_ATOMS / 64, 256, SMEM_NODE>>>(Wl2 + i * 16384, bl2 + i * 128,
                                                      Wl + i * 16384, bl + i * 128);
    }
    readout_kernel<<<N_ATOMS / 128, 128>>>(Wo1, bo1, Wo2);
    finalize_kernel<<<1, 128>>>(bo2, out);
}